// round 6
// baseline (speedup 1.0000x reference)
#include <cuda_runtime.h>
#include <cuda_bf16.h>

// BlockDiagAttention: B=4,H=16,N=4128,D=64. fp32 in/out.
// R6: split-bf16 mma + ldmatrix; 6 CTAs/SM (regs<=85 via lazy P-split and
// deferred softmax normalization: O *= 1/sum at epilogue).
#define NSEQ  4128
#define TILES 65
#define QSTR  36   // u32 per smem row (144 B)

__device__ __forceinline__ void mma16816(float c[4], const unsigned a[4],
                                         const unsigned b[2]) {
    asm volatile(
        "mma.sync.aligned.m16n8k16.row.col.f32.bf16.bf16.f32 "
        "{%0,%1,%2,%3}, {%4,%5,%6,%7}, {%8,%9}, {%0,%1,%2,%3};"
        : "+f"(c[0]), "+f"(c[1]), "+f"(c[2]), "+f"(c[3])
        : "r"(a[0]), "r"(a[1]), "r"(a[2]), "r"(a[3]), "r"(b[0]), "r"(b[1]));
}

__device__ __forceinline__ void ldsm_x4(unsigned r[4], unsigned addr) {
    asm volatile("ldmatrix.sync.aligned.m8n8.x4.shared.b16 {%0,%1,%2,%3}, [%4];"
                 : "=r"(r[0]), "=r"(r[1]), "=r"(r[2]), "=r"(r[3]) : "r"(addr));
}

__device__ __forceinline__ void ldsm_x4_t(unsigned r[4], unsigned addr) {
    asm volatile("ldmatrix.sync.aligned.m8n8.x4.trans.shared.b16 {%0,%1,%2,%3}, [%4];"
                 : "=r"(r[0]), "=r"(r[1]), "=r"(r[2]), "=r"(r[3]) : "r"(addr));
}

__device__ __forceinline__ void split2(float x0, float x1, unsigned& h, unsigned& l) {
    __nv_bfloat162 hh = __floats2bfloat162_rn(x0, x1);
    float r0 = x0 - __bfloat162float(hh.x);
    float r1 = x1 - __bfloat162float(hh.y);
    __nv_bfloat162 ll = __floats2bfloat162_rn(r0, r1);
    h = *(unsigned*)&hh;
    l = *(unsigned*)&ll;
}

extern __shared__ unsigned smem_u32[];

__global__ __launch_bounds__(128, 6)
void bd_attn_kernel(const float* __restrict__ q, const float* __restrict__ k,
                    const float* __restrict__ v, float* __restrict__ out)
{
    unsigned* sQh = smem_u32;              // later: V hi (row-major)
    unsigned* sQl = smem_u32 + 64 * QSTR;  // later: V lo
    unsigned* sKh = smem_u32 + 2 * 64 * QSTR;
    unsigned* sKl = smem_u32 + 3 * 64 * QSTR;

    const int tid  = threadIdx.x;
    const int bh   = blockIdx.x / TILES;
    const int t_   = blockIdx.x % TILES;
    const int row0 = t_ * 64;
    const int nrows = min(64, NSEQ - row0);   // 64 or 32

    const size_t base = ((size_t)bh * NSEQ + row0) * 64;
    const float* qb = q + base;
    const float* kb = k + base;
    const float* vb = v + base;

    // ---- L2 prefetch of V (consumed after GEMM1)
    {
        const char* vp = (const char*)vb;
        int lines = (nrows * 64 * 4) >> 7;
        for (int l = tid; l < lines; l += 128)
            asm volatile("prefetch.global.L2 [%0];" :: "l"(vp + (size_t)l * 128));
    }

    // ---- Load Q,K -> smem split bf16 (row-major, uint4 stores)
#pragma unroll
    for (int p = 0; p < 4; ++p) {
        int i  = tid + 128 * p;
        int r  = i >> 3;
        int c8 = (i & 7) << 3;
        float4 f0 = make_float4(0.f,0.f,0.f,0.f), f1 = f0, g0 = f0, g1 = f0;
        if (r < nrows) {
            f0 = *(const float4*)(qb + r * 64 + c8);
            f1 = *(const float4*)(qb + r * 64 + c8 + 4);
            g0 = *(const float4*)(kb + r * 64 + c8);
            g1 = *(const float4*)(kb + r * 64 + c8 + 4);
        }
        unsigned h[4], l[4];
        split2(f0.x, f0.y, h[0], l[0]); split2(f0.z, f0.w, h[1], l[1]);
        split2(f1.x, f1.y, h[2], l[2]); split2(f1.z, f1.w, h[3], l[3]);
        *(uint4*)&sQh[r * QSTR + (c8 >> 1)] = make_uint4(h[0],h[1],h[2],h[3]);
        *(uint4*)&sQl[r * QSTR + (c8 >> 1)] = make_uint4(l[0],l[1],l[2],l[3]);
        split2(g0.x, g0.y, h[0], l[0]); split2(g0.z, g0.w, h[1], l[1]);
        split2(g1.x, g1.y, h[2], l[2]); split2(g1.z, g1.w, h[3], l[3]);
        *(uint4*)&sKh[r * QSTR + (c8 >> 1)] = make_uint4(h[0],h[1],h[2],h[3]);
        *(uint4*)&sKl[r * QSTR + (c8 >> 1)] = make_uint4(l[0],l[1],l[2],l[3]);
    }
    __syncthreads();

    const int lane = tid & 31;
    const int w    = tid >> 5;
    const int g    = lane >> 2;
    const int t    = lane & 3;
    const int i8   = lane >> 3;

    const unsigned sQh_b = (unsigned)__cvta_generic_to_shared(sQh);
    const unsigned sQl_b = (unsigned)__cvta_generic_to_shared(sQl);
    const unsigned sKh_b = (unsigned)__cvta_generic_to_shared(sKh);
    const unsigned sKl_b = (unsigned)__cvta_generic_to_shared(sKl);

    const int aRow = 16 * w + (i8 & 1) * 8 + (lane & 7);
    const unsigned aOff = aRow * 144 + (i8 >> 1) * 16;
    const unsigned bOff = ((i8 >> 1) * 8 + (lane & 7)) * 144 + (i8 & 1) * 16;
    const unsigned cOff = ((i8 & 1) * 8 + (lane & 7)) * 144 + (i8 >> 1) * 16;

    // ---- GEMM1: S = Q K^T  (hh + hl + lh)
    float acc[8][4];
#pragma unroll
    for (int ch = 0; ch < 8; ++ch)
#pragma unroll
        for (int j = 0; j < 4; ++j) acc[ch][j] = 0.f;

#pragma unroll
    for (int kk = 0; kk < 4; ++kk) {
        unsigned aH[4], aL[4];
        ldsm_x4(aH, sQh_b + aOff + kk * 32);
        ldsm_x4(aL, sQl_b + aOff + kk * 32);
#pragma unroll
        for (int chp = 0; chp < 4; ++chp) {
            unsigned bH[4], bL[4];
            ldsm_x4(bH, sKh_b + bOff + chp * 2304 + kk * 32);
            ldsm_x4(bL, sKl_b + bOff + chp * 2304 + kk * 32);
            mma16816(acc[2*chp],   aH, &bH[0]);
            mma16816(acc[2*chp],   aH, &bL[0]);
            mma16816(acc[2*chp],   aL, &bH[0]);
            mma16816(acc[2*chp+1], aH, &bH[2]);
            mma16816(acc[2*chp+1], aH, &bL[2]);
            mma16816(acc[2*chp+1], aL, &bH[2]);
        }
    }

    // ---- softmax (unnormalized; normalization deferred to epilogue)
    float mx0 = -1e30f, mx1 = -1e30f;
#pragma unroll
    for (int ch = 0; ch < 8; ++ch) {
#pragma unroll
        for (int j = 0; j < 4; ++j) {
            int col = 8 * ch + 2 * t + (j & 1);
            acc[ch][j] = (col < nrows) ? acc[ch][j] * 0.125f : -1e30f;
        }
        mx0 = fmaxf(mx0, fmaxf(acc[ch][0], acc[ch][1]));
        mx1 = fmaxf(mx1, fmaxf(acc[ch][2], acc[ch][3]));
    }
    mx0 = fmaxf(mx0, __shfl_xor_sync(0xffffffffu, mx0, 1));
    mx0 = fmaxf(mx0, __shfl_xor_sync(0xffffffffu, mx0, 2));
    mx1 = fmaxf(mx1, __shfl_xor_sync(0xffffffffu, mx1, 1));
    mx1 = fmaxf(mx1, __shfl_xor_sync(0xffffffffu, mx1, 2));

    float sum0 = 0.f, sum1 = 0.f;
#pragma unroll
    for (int ch = 0; ch < 8; ++ch) {
        acc[ch][0] = __expf(acc[ch][0] - mx0);
        acc[ch][1] = __expf(acc[ch][1] - mx0);
        acc[ch][2] = __expf(acc[ch][2] - mx1);
        acc[ch][3] = __expf(acc[ch][3] - mx1);
        sum0 += acc[ch][0] + acc[ch][1];
        sum1 += acc[ch][2] + acc[ch][3];
    }
    sum0 += __shfl_xor_sync(0xffffffffu, sum0, 1);
    sum0 += __shfl_xor_sync(0xffffffffu, sum0, 2);
    sum1 += __shfl_xor_sync(0xffffffffu, sum1, 1);
    sum1 += __shfl_xor_sync(0xffffffffu, sum1, 2);

    __syncthreads();   // GEMM1 smem reads done; sQh/sQl become V hi/lo

    // ---- Load V -> smem split bf16, ROW-MAJOR
#pragma unroll
    for (int p = 0; p < 4; ++p) {
        int i  = tid + 128 * p;
        int r  = i >> 3;
        int c8 = (i & 7) << 3;
        float4 f0 = make_float4(0.f,0.f,0.f,0.f), f1 = f0;
        if (r < nrows) {
            f0 = *(const float4*)(vb + r * 64 + c8);
            f1 = *(const float4*)(vb + r * 64 + c8 + 4);
        }
        unsigned h[4], l[4];
        split2(f0.x, f0.y, h[0], l[0]); split2(f0.z, f0.w, h[1], l[1]);
        split2(f1.x, f1.y, h[2], l[2]); split2(f1.z, f1.w, h[3], l[3]);
        *(uint4*)&sQh[r * QSTR + (c8 >> 1)] = make_uint4(h[0],h[1],h[2],h[3]);
        *(uint4*)&sQl[r * QSTR + (c8 >> 1)] = make_uint4(l[0],l[1],l[2],l[3]);
    }
    __syncthreads();

    // ---- GEMM2: O = E V  (E = unnormalized probs; lazy split per kk)
    float O[8][4];
#pragma unroll
    for (int ch = 0; ch < 8; ++ch)
#pragma unroll
        for (int j = 0; j < 4; ++j) O[ch][j] = 0.f;

#pragma unroll
    for (int kk = 0; kk < 4; ++kk) {
        unsigned pH[4], pL[4];
        split2(acc[2*kk][0],   acc[2*kk][1],   pH[0], pL[0]);
        split2(acc[2*kk][2],   acc[2*kk][3],   pH[1], pL[1]);
        split2(acc[2*kk+1][0], acc[2*kk+1][1], pH[2], pL[2]);
        split2(acc[2*kk+1][2], acc[2*kk+1][3], pH[3], pL[3]);
#pragma unroll
        for (int chp = 0; chp < 4; ++chp) {
            unsigned vH[4], vL[4];
            ldsm_x4_t(vH, sQh_b + cOff + kk * 2304 + chp * 32);
            ldsm_x4_t(vL, sQl_b + cOff + kk * 2304 + chp * 32);
            mma16816(O[2*chp],   pH, &vH[0]);
            mma16816(O[2*chp],   pH, &vL[0]);
            mma16816(O[2*chp],   pL, &vH[0]);
            mma16816(O[2*chp+1], pH, &vH[2]);
            mma16816(O[2*chp+1], pH, &vL[2]);
            mma16816(O[2*chp+1], pL, &vH[2]);
        }
    }

    // ---- epilogue: normalize and write
    const float inv0 = __frcp_rn(sum0);
    const float inv1 = __frcp_rn(sum1);
    float* ob = out + base;
    const int r0 = 16 * w + g;
    const int r1 = r0 + 8;
#pragma unroll
    for (int ch = 0; ch < 8; ++ch) {
        int col = 8 * ch + 2 * t;
        if (r0 < nrows)
            *(float2*)(ob + r0 * 64 + col) =
                make_float2(O[ch][0] * inv0, O[ch][1] * inv0);
        if (r1 < nrows)
            *(float2*)(ob + r1 * 64 + col) =
                make_float2(O[ch][2] * inv1, O[ch][3] * inv1);
    }
}

extern "C" void kernel_launch(void* const* d_in, const int* in_sizes, int n_in,
                              void* d_out, int out_size) {
    const float* q = (const float*)d_in[0];
    const float* k = (const float*)d_in[1];
    const float* v = (const float*)d_in[2];
    float* out = (float*)d_out;

    const int bh = in_sizes[0] / (NSEQ * 64);                      // 64
    const int smem_bytes = 4 * 64 * QSTR * (int)sizeof(unsigned);  // 36864

    cudaFuncSetAttribute(bd_attn_kernel,
                         cudaFuncAttributeMaxDynamicSharedMemorySize, smem_bytes);
    bd_attn_kernel<<<bh * TILES, 128, smem_bytes>>>(q, k, v, out);
}